// round 14
// baseline (speedup 1.0000x reference)
#include <cuda_runtime.h>
#include <cuda_bf16.h>
#include <math.h>
#include <stdint.h>

#define SLEN   2048
#define DMODEL 1024
#define NH     16
#define HDIM   64
#define NLAYER 4
#define FFND   4096
#define OUTD   128
#define IND    64

// ======================= helpers =============================================
__device__ __forceinline__ uint32_t smem_u32(const void* p) {
    uint32_t a;
    asm("{ .reg .u64 t; cvta.to.shared.u64 t, %1; cvt.u32.u64 %0, t; }"
        : "=r"(a) : "l"(p));
    return a;
}
__device__ __forceinline__ void cp_async16(uint32_t dst, const void* src) {
    asm volatile("cp.async.cg.shared.global [%0], [%1], 16;" :: "r"(dst), "l"(src));
}
__device__ __forceinline__ void cp_commit() {
    asm volatile("cp.async.commit_group;" ::: "memory");
}
template <int NN> __device__ __forceinline__ void cp_wait() {
    asm volatile("cp.async.wait_group %0;" :: "n"(NN) : "memory");
}
__device__ __forceinline__ void ldm_x4(uint32_t* r, uint32_t addr) {
    asm volatile("ldmatrix.sync.aligned.m8n8.x4.shared.b16 {%0,%1,%2,%3}, [%4];"
                 : "=r"(r[0]), "=r"(r[1]), "=r"(r[2]), "=r"(r[3]) : "r"(addr));
}
__device__ __forceinline__ void ldm_x2(uint32_t* r, uint32_t addr) {
    asm volatile("ldmatrix.sync.aligned.m8n8.x2.shared.b16 {%0,%1}, [%2];"
                 : "=r"(r[0]), "=r"(r[1]) : "r"(addr));
}
__device__ __forceinline__ void ldm_x2_trans(uint32_t* r, uint32_t addr) {
    asm volatile("ldmatrix.sync.aligned.m8n8.x2.trans.shared.b16 {%0,%1}, [%2];"
                 : "=r"(r[0]), "=r"(r[1]) : "r"(addr));
}
__device__ __forceinline__ void mma_bf16(float* c, const uint32_t* a, const uint32_t* b) {
    asm volatile(
        "mma.sync.aligned.m16n8k16.row.col.f32.bf16.bf16.f32 "
        "{%0,%1,%2,%3}, {%4,%5,%6,%7}, {%8,%9}, {%0,%1,%2,%3};"
        : "+f"(c[0]), "+f"(c[1]), "+f"(c[2]), "+f"(c[3])
        : "r"(a[0]), "r"(a[1]), "r"(a[2]), "r"(a[3]), "r"(b[0]), "r"(b[1]));
}
__device__ __forceinline__ void split2(float x, float y, uint32_t& h, uint32_t& l) {
    __nv_bfloat16 hx = __float2bfloat16(x), hy = __float2bfloat16(y);
    __nv_bfloat16 lx = __float2bfloat16(x - __bfloat162float(hx));
    __nv_bfloat16 ly = __float2bfloat16(y - __bfloat162float(hy));
    __nv_bfloat162 hp = __halves2bfloat162(hx, hy);
    __nv_bfloat162 lp = __halves2bfloat162(lx, ly);
    h = *reinterpret_cast<uint32_t*>(&hp);
    l = *reinterpret_cast<uint32_t*>(&lp);
}

// ======================= scratch =============================================
#define LSTR    16777216u
#define OFF_L   65536u
#define OFF_OUT (65536u + 4u * LSTR)
#define WTOT    (OFF_OUT + 131072u)
__device__ __nv_bfloat16 g_whi[WTOT];
__device__ __nv_bfloat16 g_wlo[WTOT];

__device__ float g_h  [SLEN * DMODEL];
__device__ float g_qkv[SLEN * 3 * DMODEL];
__device__ float g_ct [SLEN * 32];
__device__ float g_st [SLEN * 32];
__device__ __nv_bfloat16 g_hn_hi[SLEN * DMODEL];
__device__ __nv_bfloat16 g_hn_lo[SLEN * DMODEL];
__device__ __nv_bfloat16 g_o_hi [SLEN * DMODEL];
__device__ __nv_bfloat16 g_o_lo [SLEN * DMODEL];
__device__ __nv_bfloat16 g_f_hi [SLEN * FFND];
__device__ __nv_bfloat16 g_f_lo [SLEN * FFND];
__device__ __nv_bfloat16 g_x_hi [SLEN * IND];
__device__ __nv_bfloat16 g_x_lo [SLEN * IND];

// =============== init: trig table + x hi/lo split ============================
__global__ void init_kernel(const int* __restrict__ tok_id,
                            const float* __restrict__ x,
                            float* __restrict__ ct, float* __restrict__ st,
                            __nv_bfloat16* __restrict__ xhi,
                            __nv_bfloat16* __restrict__ xlo)
{
    const int idx = blockIdx.x * blockDim.x + threadIdx.x;
    if (idx < SLEN * 32) {
        const int i = idx & 31, s = idx >> 5;
        const double inv = pow(10000.0, -(double)i / 32.0);
        const double ang = (double)tok_id[s] * inv;
        double sd, cd;
        sincos(ang, &sd, &cd);
        ct[idx] = (float)cd;
        st[idx] = (float)sd;
    } else {
        const int i = idx - SLEN * 32;
        if (i < SLEN * IND / 4) {
            const float4 v = ((const float4*)x)[i];
            uint32_t h0, l0, h1, l1;
            split2(v.x, v.y, h0, l0);
            split2(v.z, v.w, h1, l1);
            ((uint2*)xhi)[i] = make_uint2(h0, h1);
            ((uint2*)xlo)[i] = make_uint2(l0, l1);
        }
    }
}

// ======================= batched weight split (8 elems/thread) ===============
struct WSeg {
    const float* W;
    unsigned dstoff;
    int Nsrc, P, c0, grp, t8, blk0;
};
struct WTab { WSeg s[15]; int nseg; };

__global__ void __launch_bounds__(256)
wsplit_all(WTab t, __nv_bfloat16* __restrict__ hi, __nv_bfloat16* __restrict__ lo)
{
    const int b = blockIdx.x;
    int si = 0;
    #pragma unroll 1
    for (int j = 1; j < t.nseg; j++) if (b >= t.s[j].blk0) si = j;
    const WSeg sg = t.s[si];
    const int i = (b - sg.blk0) * 256 + threadIdx.x;
    if (i >= sg.t8) return;
    const int e = i * 8;
    const int k = e / sg.Nsrc, n = e - k * sg.Nsrc;
    const float4 v0 = *(const float4*)(sg.W + e);
    const float4 v1 = *(const float4*)(sg.W + e + 4);
    uint4 hw, lw;
    split2(v0.x, v0.y, hw.x, lw.x);
    split2(v0.z, v0.w, hw.y, lw.y);
    split2(v1.x, v1.y, hw.z, lw.z);
    split2(v1.z, v1.w, hw.w, lw.w);
    const int col = sg.grp ? (((n >> 3) << 4) + sg.c0) : (sg.c0 + n);
    const size_t d = sg.dstoff + (size_t)k * sg.P + col;
    *(uint4*)(hi + d) = hw;
    *(uint4*)(lo + d) = lw;
}

// ============ HMMA GEMM: bf16 hi/lo operands, 3-stage cp.async ===============
// Template on BM (128 or 64): BM=64 doubles the grid for small-N GEMMs.
#define A_PITCH 80
#define B_PITCH 272
#define B_TB    (32 * B_PITCH)

template <int BM>
__global__ void __launch_bounds__(256, 2)
hgemm_kernel(const __nv_bfloat16* __restrict__ Ahi,
             const __nv_bfloat16* __restrict__ Alo,
             const __nv_bfloat16* __restrict__ Bhi,
             const __nv_bfloat16* __restrict__ Blo,
             const float* __restrict__ bias,
             const float* __restrict__ res,
             float* __restrict__ C,
             __nv_bfloat16* __restrict__ Chi,
             __nv_bfloat16* __restrict__ Clo,
             int M, int N, int K, int Ap, int silu_mode)
{
    constexpr int A_TB    = BM * A_PITCH;
    constexpr int STAGE_B = 2 * A_TB + 2 * B_TB;
    constexpr int MT      = BM / 32;        // m-tiles per warp

    extern __shared__ char sm[];
    const uint32_t smb = smem_u32(sm);

    const int tid  = threadIdx.x;
    const int wid  = tid >> 5, lane = tid & 31;
    const int wm   = wid >> 2;
    const int wn   = wid & 3;
    const int m0 = blockIdx.y * BM, n0 = blockIdx.x * 128;
    const int nc = K >> 5;

    auto cpAB = [&](int c, int s) {
        const uint32_t stA = smb + s * STAGE_B;
        #pragma unroll
        for (int i = 0; i < BM / 32; i++) {
            const int idx  = tid + i * 256;
            const int tile = idx / (BM * 4);
            const int r    = (idx >> 2) % BM;
            const int g    = idx & 3;
            const __nv_bfloat16* src =
                (tile ? Alo : Ahi) + (size_t)(m0 + r) * Ap + c * 32 + g * 8;
            cp_async16(stA + tile * A_TB + r * A_PITCH + g * 16, src);
        }
        const uint32_t stB = stA + 2 * A_TB;
        #pragma unroll
        for (int i = 0; i < 4; i++) {
            const int idx  = tid + i * 256;
            const int tile = idx >> 9;
            const int r    = (idx >> 4) & 31;
            const int g    = idx & 15;
            const __nv_bfloat16* src =
                (tile ? Blo : Bhi) + (size_t)(c * 32 + r) * N + n0 + g * 8;
            cp_async16(stB + tile * B_TB + r * B_PITCH + g * 16, src);
        }
        cp_commit();
    };

    float acc[MT][4][4];
    #pragma unroll
    for (int a = 0; a < MT; a++)
        #pragma unroll
        for (int b = 0; b < 4; b++)
            #pragma unroll
            for (int r = 0; r < 4; r++) acc[a][b][r] = 0.f;

    cpAB(0, 0);
    if (nc > 1) cpAB(1, 1);

    for (int c = 0; c < nc; c++) {
        if (c == nc - 1) cp_wait<0>(); else cp_wait<1>();
        __syncthreads();
        if (c + 2 < nc) cpAB(c + 2, (c + 2) % 3);

        const uint32_t stage = smb + (c % 3) * STAGE_B;
        const uint32_t sAh = stage, sAl = stage + A_TB;
        const uint32_t sBh = stage + 2 * A_TB, sBl = sBh + B_TB;

        #pragma unroll
        for (int ks = 0; ks < 2; ks++) {
            uint32_t ah[MT][4], al[MT][4];
            const uint32_t acb = ks * 32 + ((lane >> 4) * 16);
            #pragma unroll
            for (int mt = 0; mt < MT; mt++) {
                const uint32_t ro =
                    (wm * (BM / 2) + mt * 16 + (lane & 15)) * A_PITCH + acb;
                ldm_x4(ah[mt], sAh + ro);
                ldm_x4(al[mt], sAl + ro);
            }
            const uint32_t brow16 = (ks * 16 + (lane & 15)) * B_PITCH;
            #pragma unroll
            for (int nt = 0; nt < 4; nt++) {
                const uint32_t co = (wn * 32 + nt * 8) * 2;
                uint32_t bh[2], bl[2];
                ldm_x2_trans(bh, sBh + brow16 + co);
                ldm_x2_trans(bl, sBl + brow16 + co);
                #pragma unroll
                for (int mt = 0; mt < MT; mt++) {
                    mma_bf16(acc[mt][nt], ah[mt], bh);
                    mma_bf16(acc[mt][nt], ah[mt], bl);
                    mma_bf16(acc[mt][nt], al[mt], bh);
                }
            }
        }
    }

    if (silu_mode) {
        const int No = N >> 1;
        #pragma unroll
        for (int mt = 0; mt < MT; mt++) {
            #pragma unroll
            for (int np = 0; np < 2; np++) {
                const int nt = np * 2;
                const int col1 = n0 + wn * 32 + nt * 8 + (lane & 3) * 2;
                const int nf = ((col1 >> 4) << 3) + (col1 & 7);
                #pragma unroll
                for (int hh = 0; hh < 2; hh++) {
                    const int row = m0 + wm * (BM / 2) + mt * 16 + (lane >> 2) + hh * 8;
                    float v0, v1;
                    {
                        const float a = acc[mt][nt][hh * 2];
                        v0 = (a / (1.0f + __expf(-a))) * acc[mt][nt + 1][hh * 2];
                        const float b = acc[mt][nt][hh * 2 + 1];
                        v1 = (b / (1.0f + __expf(-b))) * acc[mt][nt + 1][hh * 2 + 1];
                    }
                    uint32_t hw, lw;
                    split2(v0, v1, hw, lw);
                    const size_t off = (size_t)row * No + nf;
                    *(uint32_t*)(Chi + off) = hw;
                    *(uint32_t*)(Clo + off) = lw;
                }
            }
        }
    } else {
        #pragma unroll
        for (int mt = 0; mt < MT; mt++) {
            #pragma unroll
            for (int nt = 0; nt < 4; nt++) {
                const int col = n0 + wn * 32 + nt * 8 + (lane & 3) * 2;
                float bv0 = 0.f, bv1 = 0.f;
                if (bias) { bv0 = bias[col]; bv1 = bias[col + 1]; }
                #pragma unroll
                for (int hh = 0; hh < 2; hh++) {
                    const int row = m0 + wm * (BM / 2) + mt * 16 + (lane >> 2) + hh * 8;
                    float v0 = acc[mt][nt][hh * 2]     + bv0;
                    float v1 = acc[mt][nt][hh * 2 + 1] + bv1;
                    const size_t off = (size_t)row * N + col;
                    if (res) { v0 += res[off]; v1 += res[off + 1]; }
                    C[off]     = v0;
                    C[off + 1] = v1;
                }
            }
        }
    }
}

#define HG_SMEM_128 (3 * (2 * 128 * A_PITCH + 2 * B_TB))
#define HG_SMEM_64  (3 * (2 * 64 * A_PITCH + 2 * B_TB))

// ======================= RMSNorm (bf16 hi/lo output) =========================
__global__ void rmsnorm_kernel(const float* __restrict__ x,
                               const float* __restrict__ w,
                               __nv_bfloat16* __restrict__ ohi,
                               __nv_bfloat16* __restrict__ olo)
{
    const int row = blockIdx.x;
    const float* xr = x + (size_t)row * DMODEL;
    float s = 0.f;
    for (int i = threadIdx.x; i < DMODEL; i += 256) { float v = xr[i]; s += v * v; }
    #pragma unroll
    for (int off = 16; off; off >>= 1) s += __shfl_down_sync(0xffffffffu, s, off);
    __shared__ float red[8];
    const int warp = threadIdx.x >> 5, lane = threadIdx.x & 31;
    if (lane == 0) red[warp] = s;
    __syncthreads();
    if (warp == 0) {
        float t = (lane < 8) ? red[lane] : 0.f;
        #pragma unroll
        for (int off = 4; off; off >>= 1) t += __shfl_down_sync(0xffu, t, off);
        if (lane == 0) red[0] = t;
    }
    __syncthreads();
    const float inv = rsqrtf(red[0] * (1.0f / DMODEL) + 1e-5f);
    for (int i = threadIdx.x * 2; i < DMODEL; i += 512) {
        const float v0 = xr[i] * inv * w[i];
        const float v1 = xr[i + 1] * inv * w[i + 1];
        uint32_t hw, lw;
        split2(v0, v1, hw, lw);
        const size_t d = (size_t)row * DMODEL + i;
        *(uint32_t*)(ohi + d) = hw;
        *(uint32_t*)(olo + d) = lw;
    }
}

// ======================= MMA attention (FA2-style) ===========================
#define AP 72
#define ATILE (64 * AP * 2)
#define ATTN_SMEM (6 * ATILE + 512)

__global__ void __launch_bounds__(128, 4)
attn_kernel(const float* __restrict__ qkv,
            const int* __restrict__ doc_id,
            const int* __restrict__ tok_id,
            const float* __restrict__ ct,
            const float* __restrict__ st,
            __nv_bfloat16* __restrict__ ohi,
            __nv_bfloat16* __restrict__ olo)
{
    extern __shared__ char smc[];
    const uint32_t smb = smem_u32(smc);
    const uint32_t smQh = smb, smQl = smb + ATILE;
    const uint32_t smKh = smb + 2 * ATILE, smKl = smb + 3 * ATILE;
    const uint32_t smVh = smb + 4 * ATILE, smVl = smb + 5 * ATILE;
    int* docs = (int*)(smc + 6 * ATILE);
    int* toks = docs + 64;

    const int q0 = blockIdx.x * 64;
    const int h  = blockIdx.y;
    const int tid = threadIdx.x;
    const int wid = tid >> 5, lane = tid & 31;

    #pragma unroll
    for (int j = 0; j < 8; j++) {
        const int e = j * 128 + tid;
        const int r = e >> 4, i2 = (e & 15) * 2;
        const int s = q0 + r;
        const size_t base = (size_t)s * 3072 + h * HDIM;
        const float c0 = ct[s * 32 + i2],     s0 = st[s * 32 + i2];
        const float c1 = ct[s * 32 + i2 + 1], s1 = st[s * 32 + i2 + 1];
        const float xa = qkv[base + i2],      xb = qkv[base + i2 + 1];
        const float ya = qkv[base + 32 + i2], yb = qkv[base + 33 + i2];
        uint32_t hw, lw;
        split2(xa * c0 - ya * s0, xb * c1 - yb * s1, hw, lw);
        *(uint32_t*)(smc + (smQh - smb) + (r * AP + i2) * 2) = hw;
        *(uint32_t*)(smc + (smQl - smb) + (r * AP + i2) * 2) = lw;
        split2(xa * s0 + ya * c0, xb * s1 + yb * c1, hw, lw);
        *(uint32_t*)(smc + (smQh - smb) + (r * AP + 32 + i2) * 2) = hw;
        *(uint32_t*)(smc + (smQl - smb) + (r * AP + 32 + i2) * 2) = lw;
    }

    const int gq0 = q0 + wid * 16 + (lane >> 2);
    const int myDoc0 = doc_id[gq0],     myTok0 = tok_id[gq0];
    const int myDoc1 = doc_id[gq0 + 8], myTok1 = tok_id[gq0 + 8];

    __syncthreads();

    uint32_t qh[4][4], ql[4][4];
    #pragma unroll
    for (int sl = 0; sl < 4; sl++) {
        const uint32_t ro = (wid * 16 + (lane & 15)) * 144 +
                            sl * 32 + ((lane >> 4) * 16);
        ldm_x4(qh[sl], smQh + ro);
        ldm_x4(ql[sl], smQl + ro);
    }

    float mr0 = -1e29f, mr1 = -1e29f, l0 = 0.f, l1 = 0.f;
    float Oc[8][4];
    #pragma unroll
    for (int t = 0; t < 8; t++)
        #pragma unroll
        for (int r = 0; r < 4; r++) Oc[t][r] = 0.f;

    for (int ch = 0; ch < 5; ch++) {
        const int kb = q0 - 128 + ch * 64;
        __syncthreads();
        #pragma unroll
        for (int j = 0; j < 8; j++) {
            const int e = j * 128 + tid;
            const int r = e >> 4, i2 = (e & 15) * 2;
            const int kg = kb + r;
            const bool in = (kg >= 0) & (kg < SLEN);
            const int ks = in ? kg : 0;
            const size_t base = (size_t)ks * 3072 + h * HDIM;
            const float c0 = ct[ks * 32 + i2],     s0 = st[ks * 32 + i2];
            const float c1 = ct[ks * 32 + i2 + 1], s1 = st[ks * 32 + i2 + 1];
            float xa = qkv[base + 1024 + i2], xb = qkv[base + 1025 + i2];
            float ya = qkv[base + 1056 + i2], yb = qkv[base + 1057 + i2];
            uint32_t hw, lw;
            float k1a = in ? (xa * c0 - ya * s0) : 0.f;
            float k1b = in ? (xb * c1 - yb * s1) : 0.f;
            float k2a = in ? (xa * s0 + ya * c0) : 0.f;
            float k2b = in ? (xb * s1 + yb * c1) : 0.f;
            split2(k1a, k1b, hw, lw);
            *(uint32_t*)(smc + (smKh - smb) + (r * AP + i2) * 2) = hw;
            *(uint32_t*)(smc + (smKl - smb) + (r * AP + i2) * 2) = lw;
            split2(k2a, k2b, hw, lw);
            *(uint32_t*)(smc + (smKh - smb) + (r * AP + 32 + i2) * 2) = hw;
            *(uint32_t*)(smc + (smKl - smb) + (r * AP + 32 + i2) * 2) = lw;
            const float va = in ? qkv[base + 2048 + i2] : 0.f;
            const float vb = in ? qkv[base + 2049 + i2] : 0.f;
            const float vc = in ? qkv[base + 2080 + i2] : 0.f;
            const float vd = in ? qkv[base + 2081 + i2] : 0.f;
            split2(va, vb, hw, lw);
            *(uint32_t*)(smc + (smVh - smb) + (r * AP + i2) * 2) = hw;
            *(uint32_t*)(smc + (smVl - smb) + (r * AP + i2) * 2) = lw;
            split2(vc, vd, hw, lw);
            *(uint32_t*)(smc + (smVh - smb) + (r * AP + 32 + i2) * 2) = hw;
            *(uint32_t*)(smc + (smVl - smb) + (r * AP + 32 + i2) * 2) = lw;
        }
        if (tid < 64) {
            const int kg = kb + tid;
            const bool in = (kg >= 0) & (kg < SLEN);
            docs[tid] = in ? doc_id[kg] : -1;
            toks[tid] = in ? tok_id[kg] : 0;
        }
        __syncthreads();

        float sc[8][4];
        #pragma unroll
        for (int t = 0; t < 8; t++)
            #pragma unroll
            for (int r = 0; r < 4; r++) sc[t][r] = 0.f;
        #pragma unroll
        for (int sl = 0; sl < 4; sl++) {
            #pragma unroll
            for (int nt = 0; nt < 8; nt++) {
                const uint32_t ro = (nt * 8 + (lane & 7)) * 144 +
                                    sl * 32 + (((lane >> 3) & 1) * 16);
                uint32_t bh[2], bl[2];
                ldm_x2(bh, smKh + ro);
                ldm_x2(bl, smKl + ro);
                mma_bf16(sc[nt], qh[sl], bh);
                mma_bf16(sc[nt], qh[sl], bl);
                mma_bf16(sc[nt], ql[sl], bh);
            }
        }

        #pragma unroll
        for (int nt = 0; nt < 8; nt++) {
            const int kl = nt * 8 + 2 * (lane & 3);
            const int d0 = docs[kl], t0 = toks[kl];
            const int d1 = docs[kl + 1], t1 = toks[kl + 1];
            const bool ok00 = (d0 == myDoc0) && (abs(t0 - myTok0) < 128);
            const bool ok01 = (d1 == myDoc0) && (abs(t1 - myTok0) < 128);
            const bool ok10 = (d0 == myDoc1) && (abs(t0 - myTok1) < 128);
            const bool ok11 = (d1 == myDoc1) && (abs(t1 - myTok1) < 128);
            sc[nt][0] = ok00 ? sc[nt][0] * 0.125f : -1e30f;
            sc[nt][1] = ok01 ? sc[nt][1] * 0.125f : -1e30f;
            sc[nt][2] = ok10 ? sc[nt][2] * 0.125f : -1e30f;
            sc[nt][3] = ok11 ? sc[nt][3] * 0.125f : -1e30f;
        }

        float cm0 = -1e30f, cm1 = -1e30f;
        #pragma unroll
        for (int t = 0; t < 8; t++) {
            cm0 = fmaxf(cm0, fmaxf(sc[t][0], sc[t][1]));
            cm1 = fmaxf(cm1, fmaxf(sc[t][2], sc[t][3]));
        }
        cm0 = fmaxf(cm0, __shfl_xor_sync(0xffffffffu, cm0, 1));
        cm0 = fmaxf(cm0, __shfl_xor_sync(0xffffffffu, cm0, 2));
        cm1 = fmaxf(cm1, __shfl_xor_sync(0xffffffffu, cm1, 1));
        cm1 = fmaxf(cm1, __shfl_xor_sync(0xffffffffu, cm1, 2));
        const float mn0 = fmaxf(mr0, cm0), mn1 = fmaxf(mr1, cm1);
        const float es0 = __expf(mr0 - mn0), es1 = __expf(mr1 - mn1);
        mr0 = mn0; mr1 = mn1;
        l0 *= es0; l1 *= es1;
        #pragma unroll
        for (int t = 0; t < 8; t++) {
            Oc[t][0] *= es0; Oc[t][1] *= es0;
            Oc[t][2] *= es1; Oc[t][3] *= es1;
        }
        float rs0 = 0.f, rs1 = 0.f;
        #pragma unroll
        for (int t = 0; t < 8; t++) {
            sc[t][0] = __expf(sc[t][0] - mn0);
            sc[t][1] = __expf(sc[t][1] - mn0);
            sc[t][2] = __expf(sc[t][2] - mn1);
            sc[t][3] = __expf(sc[t][3] - mn1);
            rs0 += sc[t][0] + sc[t][1];
            rs1 += sc[t][2] + sc[t][3];
        }
        rs0 += __shfl_xor_sync(0xffffffffu, rs0, 1);
        rs0 += __shfl_xor_sync(0xffffffffu, rs0, 2);
        rs1 += __shfl_xor_sync(0xffffffffu, rs1, 1);
        rs1 += __shfl_xor_sync(0xffffffffu, rs1, 2);
        l0 += rs0; l1 += rs1;

        #pragma unroll
        for (int j = 0; j < 4; j++) {
            uint32_t ph[4], pl[4];
            split2(sc[2 * j][0],     sc[2 * j][1],     ph[0], pl[0]);
            split2(sc[2 * j][2],     sc[2 * j][3],     ph[1], pl[1]);
            split2(sc[2 * j + 1][0], sc[2 * j + 1][1], ph[2], pl[2]);
            split2(sc[2 * j + 1][2], sc[2 * j + 1][3], ph[3], pl[3]);
            #pragma unroll
            for (int t = 0; t < 8; t++) {
                const uint32_t ro = (j * 16 + (lane & 15)) * 144 + t * 16;
                uint32_t vh[2], vl[2];
                ldm_x2_trans(vh, smVh + ro);
                ldm_x2_trans(vl, smVl + ro);
                mma_bf16(Oc[t], ph, vh);
                mma_bf16(Oc[t], pl, vh);
                mma_bf16(Oc[t], ph, vl);
            }
        }
    }

    const float inv0 = 1.f / l0, inv1 = 1.f / l1;
    #pragma unroll
    for (int t = 0; t < 8; t++) {
        const int d = t * 8 + 2 * (lane & 3);
        uint32_t hw, lw;
        const size_t b0 = (size_t)gq0 * DMODEL + h * HDIM + d;
        split2(Oc[t][0] * inv0, Oc[t][1] * inv0, hw, lw);
        *(uint32_t*)(ohi + b0) = hw;
        *(uint32_t*)(olo + b0) = lw;
        const size_t b1 = b0 + (size_t)8 * DMODEL;
        split2(Oc[t][2] * inv1, Oc[t][3] * inv1, hw, lw);
        *(uint32_t*)(ohi + b1) = hw;
        *(uint32_t*)(olo + b1) = lw;
    }
}

// ======================= launch ==============================================
static void run_gemm(const __nv_bfloat16* Ahi, const __nv_bfloat16* Alo,
                     const __nv_bfloat16* Bhi, const __nv_bfloat16* Blo,
                     const float* bias, const float* res, float* C,
                     __nv_bfloat16* Chi, __nv_bfloat16* Clo,
                     int M, int N, int K, int Ap, int silu = 0)
{
    if (N <= 1024) {
        dim3 g(N / 128, M / 64);
        hgemm_kernel<64><<<g, 256, HG_SMEM_64>>>(Ahi, Alo, Bhi, Blo, bias, res,
                                                 C, Chi, Clo, M, N, K, Ap, silu);
    } else {
        dim3 g(N / 128, M / 128);
        hgemm_kernel<128><<<g, 256, HG_SMEM_128>>>(Ahi, Alo, Bhi, Blo, bias, res,
                                                   C, Chi, Clo, M, N, K, Ap, silu);
    }
}

static int add_seg(WTab& t, int& blk, const float* W, unsigned dstoff,
                   int K, int Nsrc, int P, int c0, int grp)
{
    const int t8 = K * Nsrc / 8;
    WSeg& s = t.s[t.nseg++];
    s.W = W; s.dstoff = dstoff; s.Nsrc = Nsrc; s.P = P;
    s.c0 = c0; s.grp = grp; s.t8 = t8; s.blk0 = blk;
    blk += (t8 + 255) / 256;
    return blk;
}

extern "C" void kernel_launch(void* const* d_in, const int* in_sizes, int n_in,
                              void* d_out, int out_size)
{
    const float* x           = (const float*)d_in[0];
    const float* emb_w       = (const float*)d_in[1];
    const float* emb_b       = (const float*)d_in[2];
    const float* wq          = (const float*)d_in[3];
    const float* wk          = (const float*)d_in[4];
    const float* wv          = (const float*)d_in[5];
    const float* wo          = (const float*)d_in[6];
    const float* attn_norm_w = (const float*)d_in[7];
    const float* ffn_norm_w  = (const float*)d_in[8];
    const float* w1          = (const float*)d_in[9];
    const float* w2          = (const float*)d_in[10];
    const float* w3          = (const float*)d_in[11];
    const float* out_norm_w  = (const float*)d_in[12];
    const float* out_w       = (const float*)d_in[13];
    const int*   doc_id      = (const int*)d_in[14];
    const int*   tok_id      = (const int*)d_in[15];
    float* out = (float*)d_out;

    cudaFuncSetAttribute(hgemm_kernel<128>,
                         cudaFuncAttributeMaxDynamicSharedMemorySize, HG_SMEM_128);
    cudaFuncSetAttribute(hgemm_kernel<64>,
                         cudaFuncAttributeMaxDynamicSharedMemorySize, HG_SMEM_64);
    cudaFuncSetAttribute(attn_kernel,
                         cudaFuncAttributeMaxDynamicSharedMemorySize, ATTN_SMEM);

    float *h, *qkv, *ct, *st;
    __nv_bfloat16 *whi, *wlo, *hnh, *hnl, *oh, *ol, *fh, *fl, *xh, *xl;
    cudaGetSymbolAddress((void**)&h,   g_h);
    cudaGetSymbolAddress((void**)&qkv, g_qkv);
    cudaGetSymbolAddress((void**)&ct,  g_ct);
    cudaGetSymbolAddress((void**)&st,  g_st);
    cudaGetSymbolAddress((void**)&whi, g_whi);
    cudaGetSymbolAddress((void**)&wlo, g_wlo);
    cudaGetSymbolAddress((void**)&hnh, g_hn_hi);
    cudaGetSymbolAddress((void**)&hnl, g_hn_lo);
    cudaGetSymbolAddress((void**)&oh,  g_o_hi);
    cudaGetSymbolAddress((void**)&ol,  g_o_lo);
    cudaGetSymbolAddress((void**)&fh,  g_f_hi);
    cudaGetSymbolAddress((void**)&fl,  g_f_lo);
    cudaGetSymbolAddress((void**)&xh,  g_x_hi);
    cudaGetSymbolAddress((void**)&xl,  g_x_lo);

    // launch 0: trig table + x split
    init_kernel<<<(SLEN * 32 + SLEN * IND / 4 + 255) / 256, 256>>>(
        tok_id, x, ct, st, xh, xl);

    // launches 1,2: batched weight split
    for (int halfi = 0; halfi < 2; halfi++) {
        WTab t;
        t.nseg = 0;
        int blk = 0;
        if (halfi == 0)
            add_seg(t, blk, emb_w, 0, IND, DMODEL, DMODEL, 0, 0);
        for (int l = halfi * 2; l < halfi * 2 + 2; l++) {
            const unsigned lb = OFF_L + (unsigned)l * LSTR;
            const size_t wqo = (size_t)l * DMODEL * DMODEL;
            const size_t wfo = (size_t)l * DMODEL * FFND;
            add_seg(t, blk, wq + wqo, lb,            DMODEL, DMODEL, 3072, 0,    0);
            add_seg(t, blk, wk + wqo, lb,            DMODEL, DMODEL, 3072, 1024, 0);
            add_seg(t, blk, wv + wqo, lb,            DMODEL, DMODEL, 3072, 2048, 0);
            add_seg(t, blk, wo + wqo, lb + 3145728,  DMODEL, DMODEL, 1024, 0,    0);
            add_seg(t, blk, w1 + wfo, lb + 4194304,  DMODEL, FFND,   8192, 0,    1);
            add_seg(t, blk, w3 + wfo, lb + 4194304,  DMODEL, FFND,   8192, 8,    1);
            add_seg(t, blk, w2 + wfo, lb + 12582912, FFND,   DMODEL, 1024, 0,    0);
        }
        if (halfi == 1)
            add_seg(t, blk, out_w, OFF_OUT, DMODEL, OUTD, OUTD, 0, 0);
        wsplit_all<<<blk, 256>>>(t, whi, wlo);
    }

    // embedding
    run_gemm(xh, xl, whi, wlo, emb_b, nullptr, h, nullptr, nullptr,
             SLEN, DMODEL, IND, IND);

    for (int l = 0; l < NLAYER; l++) {
        const __nv_bfloat16* hb = whi + OFF_L + (size_t)l * LSTR;
        const __nv_bfloat16* lb = wlo + OFF_L + (size_t)l * LSTR;

        rmsnorm_kernel<<<SLEN, 256>>>(h, attn_norm_w + (size_t)l * DMODEL, hnh, hnl);
        run_gemm(hnh, hnl, hb, lb, nullptr, nullptr, qkv, nullptr, nullptr,
                 SLEN, 3072, DMODEL, DMODEL);
        attn_kernel<<<dim3(SLEN / 64, NH), 128, ATTN_SMEM>>>(qkv, doc_id, tok_id,
                                                             ct, st, oh, ol);
        run_gemm(oh, ol, hb + 3145728, lb + 3145728, nullptr, h, h, nullptr, nullptr,
                 SLEN, DMODEL, DMODEL, DMODEL);

        rmsnorm_kernel<<<SLEN, 256>>>(h, ffn_norm_w + (size_t)l * DMODEL, hnh, hnl);
        run_gemm(hnh, hnl, hb + 4194304, lb + 4194304, nullptr, nullptr,
                 nullptr, fh, fl, SLEN, 2 * FFND, DMODEL, DMODEL, 1);
        run_gemm(fh, fl, hb + 12582912, lb + 12582912, nullptr, h, h, nullptr, nullptr,
                 SLEN, DMODEL, FFND, FFND);
    }

    rmsnorm_kernel<<<SLEN, 256>>>(h, out_norm_w, hnh, hnl);
    run_gemm(hnh, hnl, whi + OFF_OUT, wlo + OFF_OUT, nullptr, nullptr, out,
             nullptr, nullptr, SLEN, OUTD, DMODEL, DMODEL);
}

// round 15
// speedup vs baseline: 1.0292x; 1.0292x over previous
#include <cuda_runtime.h>
#include <cuda_bf16.h>
#include <math.h>
#include <stdint.h>

#define SLEN   2048
#define DMODEL 1024
#define NH     16
#define HDIM   64
#define NLAYER 4
#define FFND   4096
#define OUTD   128
#define IND    64

// ======================= helpers =============================================
__device__ __forceinline__ uint32_t smem_u32(const void* p) {
    uint32_t a;
    asm("{ .reg .u64 t; cvta.to.shared.u64 t, %1; cvt.u32.u64 %0, t; }"
        : "=r"(a) : "l"(p));
    return a;
}
__device__ __forceinline__ void cp_async16(uint32_t dst, const void* src) {
    asm volatile("cp.async.cg.shared.global [%0], [%1], 16;" :: "r"(dst), "l"(src));
}
__device__ __forceinline__ void cp_commit() {
    asm volatile("cp.async.commit_group;" ::: "memory");
}
template <int NN> __device__ __forceinline__ void cp_wait() {
    asm volatile("cp.async.wait_group %0;" :: "n"(NN) : "memory");
}
__device__ __forceinline__ void ldm_x4(uint32_t* r, uint32_t addr) {
    asm volatile("ldmatrix.sync.aligned.m8n8.x4.shared.b16 {%0,%1,%2,%3}, [%4];"
                 : "=r"(r[0]), "=r"(r[1]), "=r"(r[2]), "=r"(r[3]) : "r"(addr));
}
__device__ __forceinline__ void ldm_x4_trans(uint32_t* r, uint32_t addr) {
    asm volatile("ldmatrix.sync.aligned.m8n8.x4.trans.shared.b16 {%0,%1,%2,%3}, [%4];"
                 : "=r"(r[0]), "=r"(r[1]), "=r"(r[2]), "=r"(r[3]) : "r"(addr));
}
__device__ __forceinline__ void mma_bf16(float* c, const uint32_t* a, const uint32_t* b) {
    asm volatile(
        "mma.sync.aligned.m16n8k16.row.col.f32.bf16.bf16.f32 "
        "{%0,%1,%2,%3}, {%4,%5,%6,%7}, {%8,%9}, {%0,%1,%2,%3};"
        : "+f"(c[0]), "+f"(c[1]), "+f"(c[2]), "+f"(c[3])
        : "r"(a[0]), "r"(a[1]), "r"(a[2]), "r"(a[3]), "r"(b[0]), "r"(b[1]));
}
__device__ __forceinline__ void split2(float x, float y, uint32_t& h, uint32_t& l) {
    __nv_bfloat16 hx = __float2bfloat16(x), hy = __float2bfloat16(y);
    __nv_bfloat16 lx = __float2bfloat16(x - __bfloat162float(hx));
    __nv_bfloat16 ly = __float2bfloat16(y - __bfloat162float(hy));
    __nv_bfloat162 hp = __halves2bfloat162(hx, hy);
    __nv_bfloat162 lp = __halves2bfloat162(lx, ly);
    h = *reinterpret_cast<uint32_t*>(&hp);
    l = *reinterpret_cast<uint32_t*>(&lp);
}

// ======================= scratch =============================================
#define LSTR    16777216u
#define OFF_L   65536u
#define OFF_OUT (65536u + 4u * LSTR)
#define WTOT    (OFF_OUT + 131072u)
__device__ __nv_bfloat16 g_whi[WTOT];
__device__ __nv_bfloat16 g_wlo[WTOT];

__device__ float g_h  [SLEN * DMODEL];
__device__ float g_qkv[SLEN * 3 * DMODEL];
__device__ float g_ct [SLEN * 32];
__device__ float g_st [SLEN * 32];
__device__ __nv_bfloat16 g_hn_hi[SLEN * DMODEL];
__device__ __nv_bfloat16 g_hn_lo[SLEN * DMODEL];
__device__ __nv_bfloat16 g_o_hi [SLEN * DMODEL];
__device__ __nv_bfloat16 g_o_lo [SLEN * DMODEL];
__device__ __nv_bfloat16 g_f_hi [SLEN * FFND];
__device__ __nv_bfloat16 g_f_lo [SLEN * FFND];
__device__ __nv_bfloat16 g_x_hi [SLEN * IND];
__device__ __nv_bfloat16 g_x_lo [SLEN * IND];

// =============== init: trig table + x hi/lo split ============================
__global__ void init_kernel(const int* __restrict__ tok_id,
                            const float* __restrict__ x,
                            float* __restrict__ ct, float* __restrict__ st,
                            __nv_bfloat16* __restrict__ xhi,
                            __nv_bfloat16* __restrict__ xlo)
{
    const int idx = blockIdx.x * blockDim.x + threadIdx.x;
    if (idx < SLEN * 32) {
        const int i = idx & 31, s = idx >> 5;
        const double inv = pow(10000.0, -(double)i / 32.0);
        const double ang = (double)tok_id[s] * inv;
        double sd, cd;
        sincos(ang, &sd, &cd);
        ct[idx] = (float)cd;
        st[idx] = (float)sd;
    } else {
        const int i = idx - SLEN * 32;
        if (i < SLEN * IND / 4) {
            const float4 v = ((const float4*)x)[i];
            uint32_t h0, l0, h1, l1;
            split2(v.x, v.y, h0, l0);
            split2(v.z, v.w, h1, l1);
            ((uint2*)xhi)[i] = make_uint2(h0, h1);
            ((uint2*)xlo)[i] = make_uint2(l0, l1);
        }
    }
}

// ======================= batched weight split (8 elems/thread) ===============
struct WSeg {
    const float* W;
    unsigned dstoff;
    int Nsrc, P, c0, grp, t8, blk0;
};
struct WTab { WSeg s[15]; int nseg; };

__global__ void __launch_bounds__(256)
wsplit_all(WTab t, __nv_bfloat16* __restrict__ hi, __nv_bfloat16* __restrict__ lo)
{
    const int b = blockIdx.x;
    int si = 0;
    #pragma unroll 1
    for (int j = 1; j < t.nseg; j++) if (b >= t.s[j].blk0) si = j;
    const WSeg sg = t.s[si];
    const int i = (b - sg.blk0) * 256 + threadIdx.x;
    if (i >= sg.t8) return;
    const int e = i * 8;
    const int k = e / sg.Nsrc, n = e - k * sg.Nsrc;
    const float4 v0 = *(const float4*)(sg.W + e);
    const float4 v1 = *(const float4*)(sg.W + e + 4);
    uint4 hw, lw;
    split2(v0.x, v0.y, hw.x, lw.x);
    split2(v0.z, v0.w, hw.y, lw.y);
    split2(v1.x, v1.y, hw.z, lw.z);
    split2(v1.z, v1.w, hw.w, lw.w);
    const int col = sg.grp ? (((n >> 3) << 4) + sg.c0) : (sg.c0 + n);
    const size_t d = sg.dstoff + (size_t)k * sg.P + col;
    *(uint4*)(hi + d) = hw;
    *(uint4*)(lo + d) = lw;
}

// ============ HMMA GEMM: bf16 hi/lo operands, 3-stage cp.async ===============
#define A_PITCH 80
#define B_PITCH 272
#define B_TB    (32 * B_PITCH)

template <int BM>
__global__ void __launch_bounds__(256, 2)
hgemm_kernel(const __nv_bfloat16* __restrict__ Ahi,
             const __nv_bfloat16* __restrict__ Alo,
             const __nv_bfloat16* __restrict__ Bhi,
             const __nv_bfloat16* __restrict__ Blo,
             const float* __restrict__ bias,
             const float* __restrict__ res,
             float* __restrict__ C,
             __nv_bfloat16* __restrict__ Chi,
             __nv_bfloat16* __restrict__ Clo,
             int M, int N, int K, int Ap, int silu_mode)
{
    constexpr int A_TB    = BM * A_PITCH;
    constexpr int STAGE_B = 2 * A_TB + 2 * B_TB;
    constexpr int MT      = BM / 32;

    extern __shared__ char sm[];
    const uint32_t smb = smem_u32(sm);

    const int tid  = threadIdx.x;
    const int wid  = tid >> 5, lane = tid & 31;
    const int wm   = wid >> 2;
    const int wn   = wid & 3;
    const int m0 = blockIdx.y * BM, n0 = blockIdx.x * 128;
    const int nc = K >> 5;

    auto cpAB = [&](int c, int s) {
        const uint32_t stA = smb + s * STAGE_B;
        #pragma unroll
        for (int i = 0; i < BM / 32; i++) {
            const int idx  = tid + i * 256;
            const int tile = idx / (BM * 4);
            const int r    = (idx >> 2) % BM;
            const int g    = idx & 3;
            const __nv_bfloat16* src =
                (tile ? Alo : Ahi) + (size_t)(m0 + r) * Ap + c * 32 + g * 8;
            cp_async16(stA + tile * A_TB + r * A_PITCH + g * 16, src);
        }
        const uint32_t stB = stA + 2 * A_TB;
        #pragma unroll
        for (int i = 0; i < 4; i++) {
            const int idx  = tid + i * 256;
            const int tile = idx >> 9;
            const int r    = (idx >> 4) & 31;
            const int g    = idx & 15;
            const __nv_bfloat16* src =
                (tile ? Blo : Bhi) + (size_t)(c * 32 + r) * N + n0 + g * 8;
            cp_async16(stB + tile * B_TB + r * B_PITCH + g * 16, src);
        }
        cp_commit();
    };

    float acc[MT][4][4];
    #pragma unroll
    for (int a = 0; a < MT; a++)
        #pragma unroll
        for (int b = 0; b < 4; b++)
            #pragma unroll
            for (int r = 0; r < 4; r++) acc[a][b][r] = 0.f;

    cpAB(0, 0);
    if (nc > 1) cpAB(1, 1);

    for (int c = 0; c < nc; c++) {
        if (c == nc - 1) cp_wait<0>(); else cp_wait<1>();
        __syncthreads();
        if (c + 2 < nc) cpAB(c + 2, (c + 2) % 3);

        const uint32_t stage = smb + (c % 3) * STAGE_B;
        const uint32_t sAh = stage, sAl = stage + A_TB;
        const uint32_t sBh = stage + 2 * A_TB, sBl = sBh + B_TB;

        #pragma unroll
        for (int ks = 0; ks < 2; ks++) {
            uint32_t ah[MT][4], al[MT][4];
            const uint32_t acb = ks * 32 + ((lane >> 4) * 16);
            #pragma unroll
            for (int mt = 0; mt < MT; mt++) {
                const uint32_t ro =
                    (wm * (BM / 2) + mt * 16 + (lane & 15)) * A_PITCH + acb;
                ldm_x4(ah[mt], sAh + ro);
                ldm_x4(al[mt], sAl + ro);
            }
            // B via x4.trans: 2 n-tiles per instruction.
            // lanes 0-15: 16 k-rows at col base; lanes 16-31: same rows, col+8.
            // m0,m1 -> n-tile 2*nt2 ; m2,m3 -> n-tile 2*nt2+1.
            const uint32_t brow16 = (ks * 16 + (lane & 15)) * B_PITCH +
                                    (lane >> 4) * 16;
            #pragma unroll
            for (int nt2 = 0; nt2 < 2; nt2++) {
                const uint32_t co = (wn * 32 + nt2 * 16) * 2;
                uint32_t bh[4], bl[4];
                ldm_x4_trans(bh, sBh + brow16 + co);
                ldm_x4_trans(bl, sBl + brow16 + co);
                #pragma unroll
                for (int half = 0; half < 2; half++) {
                    const int nt = nt2 * 2 + half;
                    #pragma unroll
                    for (int mt = 0; mt < MT; mt++) {
                        mma_bf16(acc[mt][nt], ah[mt], bh + half * 2);
                        mma_bf16(acc[mt][nt], ah[mt], bl + half * 2);
                        mma_bf16(acc[mt][nt], al[mt], bh + half * 2);
                    }
                }
            }
        }
    }

    if (silu_mode) {
        const int No = N >> 1;
        #pragma unroll
        for (int mt = 0; mt < MT; mt++) {
            #pragma unroll
            for (int np = 0; np < 2; np++) {
                const int nt = np * 2;
                const int col1 = n0 + wn * 32 + nt * 8 + (lane & 3) * 2;
                const int nf = ((col1 >> 4) << 3) + (col1 & 7);
                #pragma unroll
                for (int hh = 0; hh < 2; hh++) {
                    const int row = m0 + wm * (BM / 2) + mt * 16 + (lane >> 2) + hh * 8;
                    float v0, v1;
                    {
                        const float a = acc[mt][nt][hh * 2];
                        v0 = (a / (1.0f + __expf(-a))) * acc[mt][nt + 1][hh * 2];
                        const float b = acc[mt][nt][hh * 2 + 1];
                        v1 = (b / (1.0f + __expf(-b))) * acc[mt][nt + 1][hh * 2 + 1];
                    }
                    uint32_t hw, lw;
                    split2(v0, v1, hw, lw);
                    const size_t off = (size_t)row * No + nf;
                    *(uint32_t*)(Chi + off) = hw;
                    *(uint32_t*)(Clo + off) = lw;
                }
            }
        }
    } else {
        #pragma unroll
        for (int mt = 0; mt < MT; mt++) {
            #pragma unroll
            for (int nt = 0; nt < 4; nt++) {
                const int col = n0 + wn * 32 + nt * 8 + (lane & 3) * 2;
                float bv0 = 0.f, bv1 = 0.f;
                if (bias) { bv0 = bias[col]; bv1 = bias[col + 1]; }
                #pragma unroll
                for (int hh = 0; hh < 2; hh++) {
                    const int row = m0 + wm * (BM / 2) + mt * 16 + (lane >> 2) + hh * 8;
                    float v0 = acc[mt][nt][hh * 2]     + bv0;
                    float v1 = acc[mt][nt][hh * 2 + 1] + bv1;
                    const size_t off = (size_t)row * N + col;
                    if (res) { v0 += res[off]; v1 += res[off + 1]; }
                    C[off]     = v0;
                    C[off + 1] = v1;
                }
            }
        }
    }
}

#define HG_SMEM_128 (3 * (2 * 128 * A_PITCH + 2 * B_TB))
#define HG_SMEM_64  (3 * (2 * 64 * A_PITCH + 2 * B_TB))

// ======================= RMSNorm (bf16 hi/lo output) =========================
__global__ void rmsnorm_kernel(const float* __restrict__ x,
                               const float* __restrict__ w,
                               __nv_bfloat16* __restrict__ ohi,
                               __nv_bfloat16* __restrict__ olo)
{
    const int row = blockIdx.x;
    const float* xr = x + (size_t)row * DMODEL;
    float s = 0.f;
    for (int i = threadIdx.x; i < DMODEL; i += 256) { float v = xr[i]; s += v * v; }
    #pragma unroll
    for (int off = 16; off; off >>= 1) s += __shfl_down_sync(0xffffffffu, s, off);
    __shared__ float red[8];
    const int warp = threadIdx.x >> 5, lane = threadIdx.x & 31;
    if (lane == 0) red[warp] = s;
    __syncthreads();
    if (warp == 0) {
        float t = (lane < 8) ? red[lane] : 0.f;
        #pragma unroll
        for (int off = 4; off; off >>= 1) t += __shfl_down_sync(0xffu, t, off);
        if (lane == 0) red[0] = t;
    }
    __syncthreads();
    const float inv = rsqrtf(red[0] * (1.0f / DMODEL) + 1e-5f);
    for (int i = threadIdx.x * 2; i < DMODEL; i += 512) {
        const float v0 = xr[i] * inv * w[i];
        const float v1 = xr[i + 1] * inv * w[i + 1];
        uint32_t hw, lw;
        split2(v0, v1, hw, lw);
        const size_t d = (size_t)row * DMODEL + i;
        *(uint32_t*)(ohi + d) = hw;
        *(uint32_t*)(olo + d) = lw;
    }
}

// ======================= MMA attention (FA2-style) ===========================
#define AP 72
#define ATILE (64 * AP * 2)
#define ATTN_SMEM (6 * ATILE + 512)

__global__ void __launch_bounds__(128, 4)
attn_kernel(const float* __restrict__ qkv,
            const int* __restrict__ doc_id,
            const int* __restrict__ tok_id,
            const float* __restrict__ ct,
            const float* __restrict__ st,
            __nv_bfloat16* __restrict__ ohi,
            __nv_bfloat16* __restrict__ olo)
{
    extern __shared__ char smc[];
    const uint32_t smb = smem_u32(smc);
    const uint32_t smQh = smb, smQl = smb + ATILE;
    const uint32_t smKh = smb + 2 * ATILE, smKl = smb + 3 * ATILE;
    const uint32_t smVh = smb + 4 * ATILE, smVl = smb + 5 * ATILE;
    int* docs = (int*)(smc + 6 * ATILE);
    int* toks = docs + 64;

    const int q0 = blockIdx.x * 64;
    const int h  = blockIdx.y;
    const int tid = threadIdx.x;
    const int wid = tid >> 5, lane = tid & 31;

    #pragma unroll
    for (int j = 0; j < 8; j++) {
        const int e = j * 128 + tid;
        const int r = e >> 4, i2 = (e & 15) * 2;
        const int s = q0 + r;
        const size_t base = (size_t)s * 3072 + h * HDIM;
        const float c0 = ct[s * 32 + i2],     s0 = st[s * 32 + i2];
        const float c1 = ct[s * 32 + i2 + 1], s1 = st[s * 32 + i2 + 1];
        const float xa = qkv[base + i2],      xb = qkv[base + i2 + 1];
        const float ya = qkv[base + 32 + i2], yb = qkv[base + 33 + i2];
        uint32_t hw, lw;
        split2(xa * c0 - ya * s0, xb * c1 - yb * s1, hw, lw);
        *(uint32_t*)(smc + (smQh - smb) + (r * AP + i2) * 2) = hw;
        *(uint32_t*)(smc + (smQl - smb) + (r * AP + i2) * 2) = lw;
        split2(xa * s0 + ya * c0, xb * s1 + yb * c1, hw, lw);
        *(uint32_t*)(smc + (smQh - smb) + (r * AP + 32 + i2) * 2) = hw;
        *(uint32_t*)(smc + (smQl - smb) + (r * AP + 32 + i2) * 2) = lw;
    }

    const int gq0 = q0 + wid * 16 + (lane >> 2);
    const int myDoc0 = doc_id[gq0],     myTok0 = tok_id[gq0];
    const int myDoc1 = doc_id[gq0 + 8], myTok1 = tok_id[gq0 + 8];

    __syncthreads();

    uint32_t qh[4][4], ql[4][4];
    #pragma unroll
    for (int sl = 0; sl < 4; sl++) {
        const uint32_t ro = (wid * 16 + (lane & 15)) * 144 +
                            sl * 32 + ((lane >> 4) * 16);
        ldm_x4(qh[sl], smQh + ro);
        ldm_x4(ql[sl], smQl + ro);
    }

    float mr0 = -1e29f, mr1 = -1e29f, l0 = 0.f, l1 = 0.f;
    float Oc[8][4];
    #pragma unroll
    for (int t = 0; t < 8; t++)
        #pragma unroll
        for (int r = 0; r < 4; r++) Oc[t][r] = 0.f;

    for (int ch = 0; ch < 5; ch++) {
        const int kb = q0 - 128 + ch * 64;
        __syncthreads();
        #pragma unroll
        for (int j = 0; j < 8; j++) {
            const int e = j * 128 + tid;
            const int r = e >> 4, i2 = (e & 15) * 2;
            const int kg = kb + r;
            const bool in = (kg >= 0) & (kg < SLEN);
            const int ks = in ? kg : 0;
            const size_t base = (size_t)ks * 3072 + h * HDIM;
            const float c0 = ct[ks * 32 + i2],     s0 = st[ks * 32 + i2];
            const float c1 = ct[ks * 32 + i2 + 1], s1 = st[ks * 32 + i2 + 1];
            float xa = qkv[base + 1024 + i2], xb = qkv[base + 1025 + i2];
            float ya = qkv[base + 1056 + i2], yb = qkv[base + 1057 + i2];
            uint32_t hw, lw;
            float k1a = in ? (xa * c0 - ya * s0) : 0.f;
            float k1b = in ? (xb * c1 - yb * s1) : 0.f;
            float k2a = in ? (xa * s0 + ya * c0) : 0.f;
            float k2b = in ? (xb * s1 + yb * c1) : 0.f;
            split2(k1a, k1b, hw, lw);
            *(uint32_t*)(smc + (smKh - smb) + (r * AP + i2) * 2) = hw;
            *(uint32_t*)(smc + (smKl - smb) + (r * AP + i2) * 2) = lw;
            split2(k2a, k2b, hw, lw);
            *(uint32_t*)(smc + (smKh - smb) + (r * AP + 32 + i2) * 2) = hw;
            *(uint32_t*)(smc + (smKl - smb) + (r * AP + 32 + i2) * 2) = lw;
            const float va = in ? qkv[base + 2048 + i2] : 0.f;
            const float vb = in ? qkv[base + 2049 + i2] : 0.f;
            const float vc = in ? qkv[base + 2080 + i2] : 0.f;
            const float vd = in ? qkv[base + 2081 + i2] : 0.f;
            split2(va, vb, hw, lw);
            *(uint32_t*)(smc + (smVh - smb) + (r * AP + i2) * 2) = hw;
            *(uint32_t*)(smc + (smVl - smb) + (r * AP + i2) * 2) = lw;
            split2(vc, vd, hw, lw);
            *(uint32_t*)(smc + (smVh - smb) + (r * AP + 32 + i2) * 2) = hw;
            *(uint32_t*)(smc + (smVl - smb) + (r * AP + 32 + i2) * 2) = lw;
        }
        if (tid < 64) {
            const int kg = kb + tid;
            const bool in = (kg >= 0) & (kg < SLEN);
            docs[tid] = in ? doc_id[kg] : -1;
            toks[tid] = in ? tok_id[kg] : 0;
        }
        __syncthreads();

        // ---- S = Q K^T (3-pass), K fragments via x4 (2 n-tiles / LDSM) ----
        float sc[8][4];
        #pragma unroll
        for (int t = 0; t < 8; t++)
            #pragma unroll
            for (int r = 0; r < 4; r++) sc[t][r] = 0.f;
        #pragma unroll
        for (int sl = 0; sl < 4; sl++) {
            #pragma unroll
            for (int nt2 = 0; nt2 < 4; nt2++) {
                // lanes 0-15 -> n-rows nt2*16..+7 (k0/k1 halves);
                // lanes 16-31 -> n-rows nt2*16+8..+15.
                const uint32_t ro =
                    (nt2 * 16 + (lane >> 4) * 8 + (lane & 7)) * 144 +
                    sl * 32 + ((lane >> 3) & 1) * 16;
                uint32_t bh[4], bl[4];
                ldm_x4(bh, smKh + ro);
                ldm_x4(bl, smKl + ro);
                #pragma unroll
                for (int half = 0; half < 2; half++) {
                    const int nt = nt2 * 2 + half;
                    mma_bf16(sc[nt], qh[sl], bh + half * 2);
                    mma_bf16(sc[nt], qh[sl], bl + half * 2);
                    mma_bf16(sc[nt], ql[sl], bh + half * 2);
                }
            }
        }

        #pragma unroll
        for (int nt = 0; nt < 8; nt++) {
            const int kl = nt * 8 + 2 * (lane & 3);
            const int d0 = docs[kl], t0 = toks[kl];
            const int d1 = docs[kl + 1], t1 = toks[kl + 1];
            const bool ok00 = (d0 == myDoc0) && (abs(t0 - myTok0) < 128);
            const bool ok01 = (d1 == myDoc0) && (abs(t1 - myTok0) < 128);
            const bool ok10 = (d0 == myDoc1) && (abs(t0 - myTok1) < 128);
            const bool ok11 = (d1 == myDoc1) && (abs(t1 - myTok1) < 128);
            sc[nt][0] = ok00 ? sc[nt][0] * 0.125f : -1e30f;
            sc[nt][1] = ok01 ? sc[nt][1] * 0.125f : -1e30f;
            sc[nt][2] = ok10 ? sc[nt][2] * 0.125f : -1e30f;
            sc[nt][3] = ok11 ? sc[nt][3] * 0.125f : -1e30f;
        }

        float cm0 = -1e30f, cm1 = -1e30f;
        #pragma unroll
        for (int t = 0; t < 8; t++) {
            cm0 = fmaxf(cm0, fmaxf(sc[t][0], sc[t][1]));
            cm1 = fmaxf(cm1, fmaxf(sc[t][2], sc[t][3]));
        }
        cm0 = fmaxf(cm0, __shfl_xor_sync(0xffffffffu, cm0, 1));
        cm0 = fmaxf(cm0, __shfl_xor_sync(0xffffffffu, cm0, 2));
        cm1 = fmaxf(cm1, __shfl_xor_sync(0xffffffffu, cm1, 1));
        cm1 = fmaxf(cm1, __shfl_xor_sync(0xffffffffu, cm1, 2));
        const float mn0 = fmaxf(mr0, cm0), mn1 = fmaxf(mr1, cm1);
        const float es0 = __expf(mr0 - mn0), es1 = __expf(mr1 - mn1);
        mr0 = mn0; mr1 = mn1;
        l0 *= es0; l1 *= es1;
        #pragma unroll
        for (int t = 0; t < 8; t++) {
            Oc[t][0] *= es0; Oc[t][1] *= es0;
            Oc[t][2] *= es1; Oc[t][3] *= es1;
        }
        float rs0 = 0.f, rs1 = 0.f;
        #pragma unroll
        for (int t = 0; t < 8; t++) {
            sc[t][0] = __expf(sc[t][0] - mn0);
            sc[t][1] = __expf(sc[t][1] - mn0);
            sc[t][2] = __expf(sc[t][2] - mn1);
            sc[t][3] = __expf(sc[t][3] - mn1);
            rs0 += sc[t][0] + sc[t][1];
            rs1 += sc[t][2] + sc[t][3];
        }
        rs0 += __shfl_xor_sync(0xffffffffu, rs0, 1);
        rs0 += __shfl_xor_sync(0xffffffffu, rs0, 2);
        rs1 += __shfl_xor_sync(0xffffffffu, rs1, 1);
        rs1 += __shfl_xor_sync(0xffffffffu, rs1, 2);
        l0 += rs0; l1 += rs1;

        // ---- O += P V (3-pass), V fragments via x4.trans (2 tiles / LDSM) ----
        #pragma unroll
        for (int j = 0; j < 4; j++) {
            uint32_t ph[4], pl[4];
            split2(sc[2 * j][0],     sc[2 * j][1],     ph[0], pl[0]);
            split2(sc[2 * j][2],     sc[2 * j][3],     ph[1], pl[1]);
            split2(sc[2 * j + 1][0], sc[2 * j + 1][1], ph[2], pl[2]);
            split2(sc[2 * j + 1][2], sc[2 * j + 1][3], ph[3], pl[3]);
            #pragma unroll
            for (int t2 = 0; t2 < 4; t2++) {
                const uint32_t ro = (j * 16 + (lane & 15)) * 144 +
                                    t2 * 32 + (lane >> 4) * 16;
                uint32_t vh[4], vl[4];
                ldm_x4_trans(vh, smVh + ro);
                ldm_x4_trans(vl, smVl + ro);
                #pragma unroll
                for (int half = 0; half < 2; half++) {
                    const int t = t2 * 2 + half;
                    mma_bf16(Oc[t], ph, vh + half * 2);
                    mma_bf16(Oc[t], pl, vh + half * 2);
                    mma_bf16(Oc[t], ph, vl + half * 2);
                }
            }
        }
    }

    const float inv0 = 1.f / l0, inv1 = 1.f / l1;
    #pragma unroll
    for (int t = 0; t < 8; t++) {
        const int d = t * 8 + 2 * (lane & 3);
        uint32_t hw, lw;
        const size_t b0 = (size_t)gq0 * DMODEL + h * HDIM + d;
        split2(Oc[t][0] * inv0, Oc[t][1] * inv0, hw, lw);
        *(uint32_t*)(ohi + b0) = hw;
        *(uint32_t*)(olo + b0) = lw;
        const size_t b1 = b0 + (size_t)8 * DMODEL;
        split2(Oc[t][2] * inv1, Oc[t][3] * inv1, hw, lw);
        *(uint32_t*)(ohi + b1) = hw;
        *(uint32_t*)(olo + b1) = lw;
    }
}

// ======================= launch ==============================================
static void run_gemm(const __nv_bfloat16* Ahi, const __nv_bfloat16* Alo,
                     const __nv_bfloat16* Bhi, const __nv_bfloat16* Blo,
                     const float* bias, const float* res, float* C,
                     __nv_bfloat16* Chi, __nv_bfloat16* Clo,
                     int M, int N, int K, int Ap, int silu = 0)
{
    if (N <= 1024) {
        dim3 g(N / 128, M / 64);
        hgemm_kernel<64><<<g, 256, HG_SMEM_64>>>(Ahi, Alo, Bhi, Blo, bias, res,
                                                 C, Chi, Clo, M, N, K, Ap, silu);
    } else {
        dim3 g(N / 128, M / 128);
        hgemm_kernel<128><<<g, 256, HG_SMEM_128>>>(Ahi, Alo, Bhi, Blo, bias, res,
                                                   C, Chi, Clo, M, N, K, Ap, silu);
    }
}

static int add_seg(WTab& t, int& blk, const float* W, unsigned dstoff,
                   int K, int Nsrc, int P, int c0, int grp)
{
    const int t8 = K * Nsrc / 8;
    WSeg& s = t.s[t.nseg++];
    s.W = W; s.dstoff = dstoff; s.Nsrc = Nsrc; s.P = P;
    s.c0 = c0; s.grp = grp; s.t8 = t8; s.blk0 = blk;
    blk += (t8 + 255) / 256;
    return blk;
}

extern "C" void kernel_launch(void* const* d_in, const int* in_sizes, int n_in,
                              void* d_out, int out_size)
{
    const float* x           = (const float*)d_in[0];
    const float* emb_w       = (const float*)d_in[1];
    const float* emb_b       = (const float*)d_in[2];
    const float* wq          = (const float*)d_in[3];
    const float* wk          = (const float*)d_in[4];
    const float* wv          = (const float*)d_in[5];
    const float* wo          = (const float*)d_in[6];
    const float* attn_norm_w = (const float*)d_in[7];
    const float* ffn_norm_w  = (const float*)d_in[8];
    const float* w1          = (const float*)d_in[9];
    const float* w2          = (const float*)d_in[10];
    const float* w3          = (const float*)d_in[11];
    const float* out_norm_w  = (const float*)d_in[12];
    const float* out_w       = (const float*)d_in[13];
    const int*   doc_id      = (const int*)d_in[14];
    const int*   tok_id      = (const int*)d_in[15];
    float* out = (float*)d_out;

    cudaFuncSetAttribute(hgemm_kernel<128>,
                         cudaFuncAttributeMaxDynamicSharedMemorySize, HG_SMEM_128);
    cudaFuncSetAttribute(hgemm_kernel<64>,
                         cudaFuncAttributeMaxDynamicSharedMemorySize, HG_SMEM_64);
    cudaFuncSetAttribute(attn_kernel,
                         cudaFuncAttributeMaxDynamicSharedMemorySize, ATTN_SMEM);

    float *h, *qkv, *ct, *st;
    __nv_bfloat16 *whi, *wlo, *hnh, *hnl, *oh, *ol, *fh, *fl, *xh, *xl;
    cudaGetSymbolAddress((void**)&h,   g_h);
    cudaGetSymbolAddress((void**)&qkv, g_qkv);
    cudaGetSymbolAddress((void**)&ct,  g_ct);
    cudaGetSymbolAddress((void**)&st,  g_st);
    cudaGetSymbolAddress((void**)&whi, g_whi);
    cudaGetSymbolAddress((void**)&wlo, g_wlo);
    cudaGetSymbolAddress((void**)&hnh, g_hn_hi);
    cudaGetSymbolAddress((void**)&hnl, g_hn_lo);
    cudaGetSymbolAddress((void**)&oh,  g_o_hi);
    cudaGetSymbolAddress((void**)&ol,  g_o_lo);
    cudaGetSymbolAddress((void**)&fh,  g_f_hi);
    cudaGetSymbolAddress((void**)&fl,  g_f_lo);
    cudaGetSymbolAddress((void**)&xh,  g_x_hi);
    cudaGetSymbolAddress((void**)&xl,  g_x_lo);

    init_kernel<<<(SLEN * 32 + SLEN * IND / 4 + 255) / 256, 256>>>(
        tok_id, x, ct, st, xh, xl);

    for (int halfi = 0; halfi < 2; halfi++) {
        WTab t;
        t.nseg = 0;
        int blk = 0;
        if (halfi == 0)
            add_seg(t, blk, emb_w, 0, IND, DMODEL, DMODEL, 0, 0);
        for (int l = halfi * 2; l < halfi * 2 + 2; l++) {
            const unsigned lb = OFF_L + (unsigned)l * LSTR;
            const size_t wqo = (size_t)l * DMODEL * DMODEL;
            const size_t wfo = (size_t)l * DMODEL * FFND;
            add_seg(t, blk, wq + wqo, lb,            DMODEL, DMODEL, 3072, 0,    0);
            add_seg(t, blk, wk + wqo, lb,            DMODEL, DMODEL, 3072, 1024, 0);
            add_seg(t, blk, wv + wqo, lb,            DMODEL, DMODEL, 3072, 2048, 0);
            add_seg(t, blk, wo + wqo, lb + 3145728,  DMODEL, DMODEL, 1024, 0,    0);
            add_seg(t, blk, w1 + wfo, lb + 4194304,  DMODEL, FFND,   8192, 0,    1);
            add_seg(t, blk, w3 + wfo, lb + 4194304,  DMODEL, FFND,   8192, 8,    1);
            add_seg(t, blk, w2 + wfo, lb + 12582912, FFND,   DMODEL, 1024, 0,    0);
        }
        if (halfi == 1)
            add_seg(t, blk, out_w, OFF_OUT, DMODEL, OUTD, OUTD, 0, 0);
        wsplit_all<<<blk, 256>>>(t, whi, wlo);
    }

    run_gemm(xh, xl, whi, wlo, emb_b, nullptr, h, nullptr, nullptr,
             SLEN, DMODEL, IND, IND);

    for (int l = 0; l < NLAYER; l++) {
        const __nv_bfloat16* hb = whi + OFF_L + (size_t)l * LSTR;
        const __nv_bfloat16* lb = wlo + OFF_L + (size_t)l * LSTR;

        rmsnorm_kernel<<<SLEN, 256>>>(h, attn_norm_w + (size_t)l * DMODEL, hnh, hnl);
        run_gemm(hnh, hnl, hb, lb, nullptr, nullptr, qkv, nullptr, nullptr,
                 SLEN, 3072, DMODEL, DMODEL);
        attn_kernel<<<dim3(SLEN / 64, NH), 128, ATTN_SMEM>>>(qkv, doc_id, tok_id,
                                                             ct, st, oh, ol);
        run_gemm(oh, ol, hb + 3145728, lb + 3145728, nullptr, h, h, nullptr, nullptr,
                 SLEN, DMODEL, DMODEL, DMODEL);

        rmsnorm_kernel<<<SLEN, 256>>>(h, ffn_norm_w + (size_t)l * DMODEL, hnh, hnl);
        run_gemm(hnh, hnl, hb + 4194304, lb + 4194304, nullptr, nullptr,
                 nullptr, fh, fl, SLEN, 2 * FFND, DMODEL, DMODEL, 1);
        run_gemm(fh, fl, hb + 12582912, lb + 12582912, nullptr, h, h, nullptr, nullptr,
                 SLEN, DMODEL, FFND, FFND);
    }

    rmsnorm_kernel<<<SLEN, 256>>>(h, out_norm_w, hnh, hnl);
    run_gemm(hnh, hnl, whi + OFF_OUT, wlo + OFF_OUT, nullptr, nullptr, out,
             nullptr, nullptr, SLEN, OUTD, DMODEL, DMODEL);
}